// round 12
// baseline (speedup 1.0000x reference)
#include <cuda_runtime.h>
#include <cuda_fp16.h>
#include <cstdint>

#define KDIM   256
#define BM     128
#define BN     256
#define BK     64

#define NTHREADS      576               // 512 consumers + 64 producers
#define A_STAGES      4
#define A_STAGE_BYTES (BM * BK * 2)     // 16384
#define A_TOTAL       (A_STAGES * A_STAGE_BYTES)   // 65536
#define B_CHUNK_BYTES (BN * BK * 2)     // 32768
#define B_TOTAL       (4 * B_CHUNK_BYTES)          // 131072
#define OFF_BAR       (A_TOTAL + B_TOTAL)          // 196608
#define SMEM_TOTAL    (OFF_BAR + 128)

// W^T in fp16: g_Wt[n][k] = half(W[k][n])
__device__ __align__(256) __half g_Wt[KDIM * KDIM];

// ---------------- helpers ----------------
__device__ __forceinline__ uint32_t smem_u32(const void* p) {
    uint32_t a;
    asm("{ .reg .u64 t; cvta.to.shared.u64 t, %1; cvt.u32.u64 %0, t; }" : "=r"(a) : "l"(p));
    return a;
}
__device__ __forceinline__ void cp16(uint32_t dst, const void* src) {
    asm volatile("cp.async.cg.shared.global [%0], [%1], 16;" :: "r"(dst), "l"(src));
}
__device__ __forceinline__ void cp_commit() {
    asm volatile("cp.async.commit_group;" ::: "memory");
}
template <int N> __device__ __forceinline__ void cp_wait() {
    asm volatile("cp.async.wait_group %0;" :: "n"(N) : "memory");
}
#define MBAR_INIT(addr, cnt) \
    asm volatile("mbarrier.init.shared.b64 [%0], %1;" :: "r"(addr), "r"(cnt) : "memory")
#define MBAR_ARRIVE(addr) \
    asm volatile("mbarrier.arrive.shared.b64 _, [%0];" :: "r"(addr) : "memory")
#define MBAR_WAIT(addr, par) do {                                                   \
    uint32_t _m = (addr), _p = (par), _d;                                           \
    asm volatile("{ .reg .pred p; mbarrier.try_wait.parity.acquire.cta.shared::cta.b64 p, [%1], %2; selp.b32 %0, 1, 0, p; }" \
                 : "=r"(_d) : "r"(_m), "r"(_p) : "memory");                         \
    if (!_d) {                                                                      \
        asm volatile("{ .reg .pred P; L%=: mbarrier.try_wait.parity.acquire.cta.shared::cta.b64 P, [%0], %1, 0x989680; @P bra D%=; bra L%=; D%=: }" \
                     :: "r"(_m), "r"(_p) : "memory");                               \
    } } while (0)

#define LDSM4(r0, r1, r2, r3, a)                                                 \
    asm volatile("ldmatrix.sync.aligned.m8n8.x4.shared.b16 {%0,%1,%2,%3}, [%4];" \
                 : "=r"(r0), "=r"(r1), "=r"(r2), "=r"(r3) : "r"(a))

__device__ __forceinline__ void mma_fp16(float* d, const uint32_t* a,
                                         uint32_t b0, uint32_t b1) {
    asm volatile(
        "mma.sync.aligned.m16n8k16.row.col.f32.f16.f16.f32 "
        "{%0,%1,%2,%3}, {%4,%5,%6,%7}, {%8,%9}, {%0,%1,%2,%3};"
        : "+f"(d[0]), "+f"(d[1]), "+f"(d[2]), "+f"(d[3])
        : "r"(a[0]), "r"(a[1]), "r"(a[2]), "r"(a[3]), "r"(b0), "r"(b1));
}

// ---------------- prep: W[K,N] fp32 -> Wt[N,K] fp16 ----------------
__global__ void prep_wt_kernel(const float* __restrict__ W) {
    int n = blockIdx.x, k = threadIdx.x;
    g_Wt[n * KDIM + k] = __float2half_rn(W[k * KDIM + n]);
}

// ---------------- main GEMM: warp-specialized, persistent, B resident,
//                  16 consumer warps (64x32 tile) ----------------
__global__ __launch_bounds__(NTHREADS, 1)
void cp2d_fp16_kernel(const float* __restrict__ x, float* __restrict__ out,
                      int G, int NT) {
    extern __shared__ __align__(128) char smem[];
    const uint32_t sb = smem_u32(smem);

    const int tid  = threadIdx.x;
    const int lane = tid & 31;
    const int warp = tid >> 5;
    const int bid  = blockIdx.x;

    const int my_tiles = (NT - bid + G - 1) / G;
    if (my_tiles <= 0) return;
    const int GG = my_tiles * 4;

    auto m_of = [&](int gg) -> long {
        return ((long)bid + (long)(gg >> 2) * G) * BM;
    };
    auto fullB  = [&](int s) -> uint32_t { return sb + OFF_BAR + s * 16; };
    auto emptyB = [&](int s) -> uint32_t { return sb + OFF_BAR + s * 16 + 8; };

    // ---- init barriers ----
    if (tid == 0) {
#pragma unroll
        for (int s = 0; s < A_STAGES; s++) {
            MBAR_INIT(fullB(s), 64);     // 64 producer threads arrive
            MBAR_INIT(emptyB(s), 512);   // 512 consumer threads arrive
        }
    }

    // ---- cooperative B load (once, resident) ----
    for (int i = tid; i < 8192; i += NTHREADS) {     // 8192 x 16B units
        const int c = i >> 11;            // chunk
        const int n = (i >> 3) & 255;     // B row
        const int u = i & 7;              // 16B unit in row
        uint32_t dst = sb + A_TOTAL + (uint32_t)c * B_CHUNK_BYTES +
                       n * 128 + ((u ^ (n & 7)) << 4);
        cp16(dst, g_Wt + n * KDIM + c * BK + u * 8);
    }
    cp_commit();
    cp_wait<0>();
    __syncthreads();     // B resident + barriers initialized, visible to all

    if (warp >= 16) {
        // ================= PRODUCER (warps 16,17: 64 threads) =================
        const int ptid  = tid - 512;
        const int a_f   = ptid & 15;          // float4 index along k
        const int a_r0  = ptid >> 4;          // 0..3; rows a_r0 + j*4
        const int u     = a_f >> 1;
        const int off8  = (a_f & 1) * 8;

        for (int gg = 0; gg < GG; gg++) {
            const int stage = gg & 3;
            const int phase = 1 ^ ((gg >> 2) & 1);    // start-flipped
            MBAR_WAIT(emptyB(stage), phase);

            const long m0 = m_of(gg);
            const int  k0 = (gg & 3) * BK;
            const uint32_t aBase = sb + (uint32_t)stage * A_STAGE_BYTES;
            // two batches of 16 float4 to bound register use
#pragma unroll
            for (int h = 0; h < 2; h++) {
                float4 v[16];
#pragma unroll
                for (int j = 0; j < 16; j++)
                    v[j] = *(const float4*)(x + (m0 + a_r0 + (h * 16 + j) * 4) * KDIM
                                            + k0 + a_f * 4);
#pragma unroll
                for (int j = 0; j < 16; j++) {
                    const int row = a_r0 + (h * 16 + j) * 4;
                    uint32_t addr = aBase + row * 128 + ((u ^ (row & 7)) << 4) + off8;
                    __half2 h0 = __floats2half2_rn(v[j].x, v[j].y);
                    __half2 h1 = __floats2half2_rn(v[j].z, v[j].w);
                    asm volatile("st.shared.v2.b32 [%0], {%1, %2};"
                                 :: "r"(addr), "r"(*(uint32_t*)&h0), "r"(*(uint32_t*)&h1));
                }
            }
            MBAR_ARRIVE(fullB(stage));
        }
    } else {
        // ================= CONSUMER (warps 0..15: 512 threads) =================
        const int wm = warp & 1;          // 2 warps along M (64 rows)
        const int wn = warp >> 1;         // 8 warps along N (32 cols each)

        const int la_row = (lane & 7) + ((lane >> 3) & 1) * 8;
        const int la_u   = lane >> 4;
        const int lb_row = (lane & 7) + ((lane >> 4) & 1) * 8;
        const int lb_u   = (lane >> 3) & 1;

        float acc[4][4][4];               // 64 regs: 4 m-tiles x 4 n-tiles
#pragma unroll
        for (int mt = 0; mt < 4; mt++)
#pragma unroll
            for (int nt = 0; nt < 4; nt++)
#pragma unroll
                for (int i = 0; i < 4; i++) acc[mt][nt][i] = 0.f;

        for (int gg = 0; gg < GG; gg++) {
            const int stage = gg & 3;
            const int phase = (gg >> 2) & 1;
            MBAR_WAIT(fullB(stage), phase);

            const uint32_t aBase = sb + (uint32_t)stage * A_STAGE_BYTES;
            const uint32_t bBase = sb + A_TOTAL + (uint32_t)stage * B_CHUNK_BYTES;
#pragma unroll
            for (int ks = 0; ks < 4; ks++) {
                const int u0 = ks * 2;
                uint32_t b[2][4];         // 2 LDSM4 -> 4 n-tiles (8 cols each)
#pragma unroll
                for (int nt2 = 0; nt2 < 2; nt2++) {
                    const int row = wn * 32 + nt2 * 16 + lb_row;
                    uint32_t addr = bBase + row * 128 + (((u0 + lb_u) ^ (row & 7)) << 4);
                    LDSM4(b[nt2][0], b[nt2][1], b[nt2][2], b[nt2][3], addr);
                }
#pragma unroll
                for (int mt = 0; mt < 4; mt++) {
                    uint32_t a[4];
                    const int row = wm * 64 + mt * 16 + la_row;
                    uint32_t addr = aBase + row * 128 + (((u0 + la_u) ^ (row & 7)) << 4);
                    LDSM4(a[0], a[1], a[2], a[3], addr);
#pragma unroll
                    for (int nt2 = 0; nt2 < 2; nt2++)
#pragma unroll
                        for (int s = 0; s < 2; s++) {
                            const int nt = nt2 * 2 + s;
                            mma_fp16(acc[mt][nt], a, b[nt2][2 * s], b[nt2][2 * s + 1]);
                        }
                }
            }
            MBAR_ARRIVE(emptyB(stage));   // stage consumed; producers may refill

            if ((gg & 3) == 3) {
                const long m0 = m_of(gg);
                const int er = lane >> 2;
                const int ec = (lane & 3) * 2;
#pragma unroll
                for (int mt = 0; mt < 4; mt++) {
                    const long r0 = m0 + wm * 64 + mt * 16 + er;
#pragma unroll
                    for (int nt = 0; nt < 4; nt++) {
                        const int col = wn * 32 + nt * 8 + ec;
                        *(float2*)(out + r0 * KDIM + col) =
                            make_float2(acc[mt][nt][0], acc[mt][nt][1]);
                        *(float2*)(out + (r0 + 8) * KDIM + col) =
                            make_float2(acc[mt][nt][2], acc[mt][nt][3]);
                    }
                }
#pragma unroll
                for (int mt = 0; mt < 4; mt++)
#pragma unroll
                    for (int nt = 0; nt < 4; nt++)
#pragma unroll
                        for (int i = 0; i < 4; i++) acc[mt][nt][i] = 0.f;
            }
        }
    }
}

extern "C" void kernel_launch(void* const* d_in, const int* in_sizes, int n_in,
                              void* d_out, int out_size) {
    const float* x = (const float*)d_in[0];
    const float* W = (const float*)d_in[1];
    float* out = (float*)d_out;

    const int M  = in_sizes[0] / KDIM;   // 401408
    const int NT = M / BM;               // 3136 tiles

    int nsm = 0;
    cudaDeviceGetAttribute(&nsm, cudaDevAttrMultiProcessorCount, 0);
    if (nsm <= 0) nsm = 148;
    if (nsm > NT) nsm = NT;

    cudaFuncSetAttribute(cp2d_fp16_kernel,
                         cudaFuncAttributeMaxDynamicSharedMemorySize, SMEM_TOTAL);

    prep_wt_kernel<<<KDIM, KDIM>>>(W);
    cp2d_fp16_kernel<<<nsm, NTHREADS, SMEM_TOTAL>>>(x, out, nsm, NT);
}

// round 13
// speedup vs baseline: 1.1853x; 1.1853x over previous
#include <cuda_runtime.h>
#include <cuda_fp16.h>
#include <cstdint>

#define KDIM   256
#define BM     128
#define BN     256
#define BK     128                      // 2 chunks per tile

#define NTHREADS      320               // 256 consumers + 64 producers
#define A_STAGES      3
#define A_SUB_BYTES   (BM * 64 * 2)     // 16384 (one 64-k sub-chunk)
#define A_STAGE_BYTES (2 * A_SUB_BYTES) // 32768 (BK=128)
#define A_TOTAL       (A_STAGES * A_STAGE_BYTES)   // 98304
#define B_CHUNK_BYTES (BN * 64 * 2)     // 32768 (per 64-k chunk)
#define B_TOTAL       (4 * B_CHUNK_BYTES)          // 131072
#define OFF_BAR       (A_TOTAL + B_TOTAL)          // 229376
#define SMEM_TOTAL    (OFF_BAR + 128)   // 229504 < 227KB cap

// W^T in fp16: g_Wt[n][k] = half(W[k][n])
__device__ __align__(256) __half g_Wt[KDIM * KDIM];

// ---------------- helpers ----------------
__device__ __forceinline__ uint32_t smem_u32(const void* p) {
    uint32_t a;
    asm("{ .reg .u64 t; cvta.to.shared.u64 t, %1; cvt.u32.u64 %0, t; }" : "=r"(a) : "l"(p));
    return a;
}
__device__ __forceinline__ void cp16(uint32_t dst, const void* src) {
    asm volatile("cp.async.cg.shared.global [%0], [%1], 16;" :: "r"(dst), "l"(src));
}
__device__ __forceinline__ void cp_commit() {
    asm volatile("cp.async.commit_group;" ::: "memory");
}
template <int N> __device__ __forceinline__ void cp_wait() {
    asm volatile("cp.async.wait_group %0;" :: "n"(N) : "memory");
}
#define MBAR_INIT(addr, cnt) \
    asm volatile("mbarrier.init.shared.b64 [%0], %1;" :: "r"(addr), "r"(cnt) : "memory")
#define MBAR_ARRIVE(addr) \
    asm volatile("mbarrier.arrive.shared.b64 _, [%0];" :: "r"(addr) : "memory")
#define MBAR_WAIT(addr, par) do {                                                   \
    uint32_t _m = (addr), _p = (par), _d;                                           \
    asm volatile("{ .reg .pred p; mbarrier.try_wait.parity.acquire.cta.shared::cta.b64 p, [%1], %2; selp.b32 %0, 1, 0, p; }" \
                 : "=r"(_d) : "r"(_m), "r"(_p) : "memory");                         \
    if (!_d) {                                                                      \
        asm volatile("{ .reg .pred P; L%=: mbarrier.try_wait.parity.acquire.cta.shared::cta.b64 P, [%0], %1, 0x989680; @P bra D%=; bra L%=; D%=: }" \
                     :: "r"(_m), "r"(_p) : "memory");                               \
    } } while (0)

#define LDSM4(r0, r1, r2, r3, a)                                                 \
    asm volatile("ldmatrix.sync.aligned.m8n8.x4.shared.b16 {%0,%1,%2,%3}, [%4];" \
                 : "=r"(r0), "=r"(r1), "=r"(r2), "=r"(r3) : "r"(a))

__device__ __forceinline__ void mma_fp16(float* d, const uint32_t* a,
                                         uint32_t b0, uint32_t b1) {
    asm volatile(
        "mma.sync.aligned.m16n8k16.row.col.f32.f16.f16.f32 "
        "{%0,%1,%2,%3}, {%4,%5,%6,%7}, {%8,%9}, {%0,%1,%2,%3};"
        : "+f"(d[0]), "+f"(d[1]), "+f"(d[2]), "+f"(d[3])
        : "r"(a[0]), "r"(a[1]), "r"(a[2]), "r"(a[3]), "r"(b0), "r"(b1));
}

// ---------------- prep: W[K,N] fp32 -> Wt[N,K] fp16 ----------------
__global__ void prep_wt_kernel(const float* __restrict__ W) {
    int n = blockIdx.x, k = threadIdx.x;
    g_Wt[n * KDIM + k] = __float2half_rn(W[k * KDIM + n]);
}

// ---------------- main GEMM: warp-specialized, persistent, B resident, BK=128 ----------------
__global__ __launch_bounds__(NTHREADS, 1)
void cp2d_fp16_kernel(const float* __restrict__ x, float* __restrict__ out,
                      int G, int NT) {
    extern __shared__ __align__(128) char smem[];
    const uint32_t sb = smem_u32(smem);

    const int tid  = threadIdx.x;
    const int lane = tid & 31;
    const int warp = tid >> 5;
    const int bid  = blockIdx.x;

    const int my_tiles = (NT - bid + G - 1) / G;
    if (my_tiles <= 0) return;
    const int GG = my_tiles * 2;                  // 2 chunks (BK=128) per tile

    auto m_of = [&](int gg) -> long {
        return ((long)bid + (long)(gg >> 1) * G) * BM;
    };
    auto fullB  = [&](int s) -> uint32_t { return sb + OFF_BAR + s * 16; };
    auto emptyB = [&](int s) -> uint32_t { return sb + OFF_BAR + s * 16 + 8; };

    // ---- init barriers ----
    if (tid == 0) {
#pragma unroll
        for (int s = 0; s < A_STAGES; s++) {
            MBAR_INIT(fullB(s), 64);     // producer threads
            MBAR_INIT(emptyB(s), 256);   // consumer threads
        }
    }

    // ---- cooperative B load (once, resident; same layout as before) ----
    for (int i = tid; i < 8192; i += NTHREADS) {     // 8192 x 16B units
        const int c = i >> 11;            // 64-k chunk
        const int n = (i >> 3) & 255;     // B row
        const int u = i & 7;              // 16B unit in row
        uint32_t dst = sb + A_TOTAL + (uint32_t)c * B_CHUNK_BYTES +
                       n * 128 + ((u ^ (n & 7)) << 4);
        cp16(dst, g_Wt + n * KDIM + c * 64 + u * 8);
    }
    cp_commit();
    cp_wait<0>();
    __syncthreads();     // B resident + barriers initialized

    if (warp >= 8) {
        // ================= PRODUCER (warps 8,9: 64 threads) =================
        const int ptid  = tid - 256;
        const int a_f   = ptid & 15;          // float4 index within 64-k sub-chunk
        const int a_r0  = ptid >> 4;          // 0..3; rows a_r0 + j*4
        const int u     = a_f >> 1;
        const int off8  = (a_f & 1) * 8;

        int st = 0, ph = 1;                   // start-flipped
        for (int gg = 0; gg < GG; gg++) {
            MBAR_WAIT(emptyB(st), ph);

            const long m0 = m_of(gg);
            const int  k0 = (gg & 1) * BK;    // 0 or 128
            const uint32_t aBase = sb + (uint32_t)st * A_STAGE_BYTES;
#pragma unroll
            for (int sub = 0; sub < 2; sub++) {
                const uint32_t sBase = aBase + sub * A_SUB_BYTES;
                const int ks0 = k0 + sub * 64;
#pragma unroll
                for (int h = 0; h < 2; h++) {
                    float4 v[16];
#pragma unroll
                    for (int j = 0; j < 16; j++)
                        v[j] = *(const float4*)(x + (m0 + a_r0 + (h * 16 + j) * 4) * KDIM
                                                + ks0 + a_f * 4);
#pragma unroll
                    for (int j = 0; j < 16; j++) {
                        const int row = a_r0 + (h * 16 + j) * 4;
                        uint32_t addr = sBase + row * 128 + ((u ^ (row & 7)) << 4) + off8;
                        __half2 h0 = __floats2half2_rn(v[j].x, v[j].y);
                        __half2 h1 = __floats2half2_rn(v[j].z, v[j].w);
                        asm volatile("st.shared.v2.b32 [%0], {%1, %2};"
                                     :: "r"(addr), "r"(*(uint32_t*)&h0), "r"(*(uint32_t*)&h1));
                    }
                }
            }
            MBAR_ARRIVE(fullB(st));
            if (++st == A_STAGES) { st = 0; ph ^= 1; }
        }
    } else {
        // ================= CONSUMER (warps 0..7: 256 threads) =================
        const int wm = warp & 1;          // 2 warps along M (64 rows)
        const int wn = warp >> 1;         // 4 warps along N (64 cols)

        const int la_row = (lane & 7) + ((lane >> 3) & 1) * 8;
        const int la_u   = lane >> 4;
        const int lb_row = (lane & 7) + ((lane >> 4) & 1) * 8;
        const int lb_u   = (lane >> 3) & 1;

        float acc[4][8][4];
#pragma unroll
        for (int mt = 0; mt < 4; mt++)
#pragma unroll
            for (int nt = 0; nt < 8; nt++)
#pragma unroll
                for (int i = 0; i < 4; i++) acc[mt][nt][i] = 0.f;

        int st = 0, ph = 0;
        for (int gg = 0; gg < GG; gg++) {
            MBAR_WAIT(fullB(st), ph);

            const uint32_t aBase = sb + (uint32_t)st * A_STAGE_BYTES;
            const uint32_t bHalf = sb + A_TOTAL + (uint32_t)(gg & 1) * (2 * B_CHUNK_BYTES);
#pragma unroll
            for (int ks = 0; ks < 8; ks++) {
                const int sub = ks >> 2;
                const int u0  = (ks & 3) * 2;
                const uint32_t aSub = aBase + sub * A_SUB_BYTES;
                const uint32_t bBase = bHalf + sub * B_CHUNK_BYTES;
                uint32_t b[4][4];
#pragma unroll
                for (int nt2 = 0; nt2 < 4; nt2++) {
                    const int row = wn * 64 + nt2 * 16 + lb_row;
                    uint32_t addr = bBase + row * 128 + (((u0 + lb_u) ^ (row & 7)) << 4);
                    LDSM4(b[nt2][0], b[nt2][1], b[nt2][2], b[nt2][3], addr);
                }
#pragma unroll
                for (int mt = 0; mt < 4; mt++) {
                    uint32_t a[4];
                    const int row = wm * 64 + mt * 16 + la_row;
                    uint32_t addr = aSub + row * 128 + (((u0 + la_u) ^ (row & 7)) << 4);
                    LDSM4(a[0], a[1], a[2], a[3], addr);
#pragma unroll
                    for (int nt2 = 0; nt2 < 4; nt2++)
#pragma unroll
                        for (int s = 0; s < 2; s++) {
                            const int nt = nt2 * 2 + s;
                            mma_fp16(acc[mt][nt], a, b[nt2][2 * s], b[nt2][2 * s + 1]);
                        }
                }
            }
            MBAR_ARRIVE(emptyB(st));
            if (++st == A_STAGES) { st = 0; ph ^= 1; }

            if (gg & 1) {
                const long m0 = m_of(gg);
                const int er = lane >> 2;
                const int ec = (lane & 3) * 2;
#pragma unroll
                for (int mt = 0; mt < 4; mt++) {
                    const long r0 = m0 + wm * 64 + mt * 16 + er;
#pragma unroll
                    for (int nt = 0; nt < 8; nt++) {
                        const int col = wn * 64 + nt * 8 + ec;
                        *(float2*)(out + r0 * KDIM + col) =
                            make_float2(acc[mt][nt][0], acc[mt][nt][1]);
                        *(float2*)(out + (r0 + 8) * KDIM + col) =
                            make_float2(acc[mt][nt][2], acc[mt][nt][3]);
                    }
                }
#pragma unroll
                for (int mt = 0; mt < 4; mt++)
#pragma unroll
                    for (int nt = 0; nt < 8; nt++)
#pragma unroll
                        for (int i = 0; i < 4; i++) acc[mt][nt][i] = 0.f;
            }
        }
    }
}

extern "C" void kernel_launch(void* const* d_in, const int* in_sizes, int n_in,
                              void* d_out, int out_size) {
    const float* x = (const float*)d_in[0];
    const float* W = (const float*)d_in[1];
    float* out = (float*)d_out;

    const int M  = in_sizes[0] / KDIM;   // 401408
    const int NT = M / BM;               // 3136 tiles

    int nsm = 0;
    cudaDeviceGetAttribute(&nsm, cudaDevAttrMultiProcessorCount, 0);
    if (nsm <= 0) nsm = 148;
    if (nsm > NT) nsm = NT;

    cudaFuncSetAttribute(cp2d_fp16_kernel,
                         cudaFuncAttributeMaxDynamicSharedMemorySize, SMEM_TOTAL);

    prep_wt_kernel<<<KDIM, KDIM>>>(W);
    cp2d_fp16_kernel<<<nsm, NTHREADS, SMEM_TOTAL>>>(x, out, nsm, NT);
}

// round 14
// speedup vs baseline: 1.4123x; 1.1915x over previous
#include <cuda_runtime.h>
#include <cuda_fp16.h>
#include <cstdint>

#define KDIM   256
#define BM     128
#define BN     256
#define BK     64

#define NTHREADS      320               // 256 consumers + 64 producers
#define A_STAGES      4
#define A_STAGE_BYTES (BM * BK * 2)     // 16384
#define A_TOTAL       (A_STAGES * A_STAGE_BYTES)   // 65536
#define B_CHUNK_BYTES (BN * BK * 2)     // 32768
#define B_TOTAL       (4 * B_CHUNK_BYTES)          // 131072
#define OFF_BAR       (A_TOTAL + B_TOTAL)          // 196608
#define SMEM_TOTAL    (OFF_BAR + 128)

// W^T in fp16: g_Wt[n][k] = half(W[k][n])
__device__ __align__(256) __half g_Wt[KDIM * KDIM];

// ---------------- helpers ----------------
__device__ __forceinline__ uint32_t smem_u32(const void* p) {
    uint32_t a;
    asm("{ .reg .u64 t; cvta.to.shared.u64 t, %1; cvt.u32.u64 %0, t; }" : "=r"(a) : "l"(p));
    return a;
}
__device__ __forceinline__ void cp16(uint32_t dst, const void* src) {
    asm volatile("cp.async.cg.shared.global [%0], [%1], 16;" :: "r"(dst), "l"(src));
}
__device__ __forceinline__ void cp_commit() {
    asm volatile("cp.async.commit_group;" ::: "memory");
}
template <int N> __device__ __forceinline__ void cp_wait() {
    asm volatile("cp.async.wait_group %0;" :: "n"(N) : "memory");
}
#define MBAR_INIT(addr, cnt) \
    asm volatile("mbarrier.init.shared.b64 [%0], %1;" :: "r"(addr), "r"(cnt) : "memory")
#define MBAR_ARRIVE(addr) \
    asm volatile("mbarrier.arrive.shared.b64 _, [%0];" :: "r"(addr) : "memory")
#define MBAR_WAIT(addr, par) do {                                                   \
    uint32_t _m = (addr), _p = (par), _d;                                           \
    asm volatile("{ .reg .pred p; mbarrier.try_wait.parity.acquire.cta.shared::cta.b64 p, [%1], %2; selp.b32 %0, 1, 0, p; }" \
                 : "=r"(_d) : "r"(_m), "r"(_p) : "memory");                         \
    if (!_d) {                                                                      \
        asm volatile("{ .reg .pred P; L%=: mbarrier.try_wait.parity.acquire.cta.shared::cta.b64 P, [%0], %1, 0x989680; @P bra D%=; bra L%=; D%=: }" \
                     :: "r"(_m), "r"(_p) : "memory");                               \
    } } while (0)

#define LDSM4(r0, r1, r2, r3, a)                                                 \
    asm volatile("ldmatrix.sync.aligned.m8n8.x4.shared.b16 {%0,%1,%2,%3}, [%4];" \
                 : "=r"(r0), "=r"(r1), "=r"(r2), "=r"(r3) : "r"(a))

__device__ __forceinline__ void mma_fp16(float* d, const uint32_t* a,
                                         uint32_t b0, uint32_t b1) {
    asm volatile(
        "mma.sync.aligned.m16n8k16.row.col.f32.f16.f16.f32 "
        "{%0,%1,%2,%3}, {%4,%5,%6,%7}, {%8,%9}, {%0,%1,%2,%3};"
        : "+f"(d[0]), "+f"(d[1]), "+f"(d[2]), "+f"(d[3])
        : "r"(a[0]), "r"(a[1]), "r"(a[2]), "r"(a[3]), "r"(b0), "r"(b1));
}

// ---------------- prep: W[K,N] fp32 -> Wt[N,K] fp16 (coalesced tiled transpose) ----------------
__global__ void prep_wt_kernel(const float* __restrict__ W) {
    __shared__ float t[32][33];
    const int tx = threadIdx.x, ty = threadIdx.y;
    const int bn = blockIdx.x * 32;     // n tile base
    const int bk = blockIdx.y * 32;     // k tile base
    // coalesced read: W[k][n], n contiguous
    t[ty][tx] = W[(bk + ty) * KDIM + bn + tx];
    __syncthreads();
    // coalesced write: Wt[n][k], k contiguous
    g_Wt[(bn + ty) * KDIM + bk + tx] = __float2half_rn(t[tx][ty]);
}

// ---------------- main GEMM: warp-specialized, persistent, B resident, ks-skewed ----------------
__global__ __launch_bounds__(NTHREADS, 1)
void cp2d_fp16_kernel(const float* __restrict__ x, float* __restrict__ out,
                      int G, int NT) {
    extern __shared__ __align__(128) char smem[];
    const uint32_t sb = smem_u32(smem);

    const int tid  = threadIdx.x;
    const int lane = tid & 31;
    const int warp = tid >> 5;
    const int bid  = blockIdx.x;

    const int my_tiles = (NT - bid + G - 1) / G;
    if (my_tiles <= 0) return;
    const int GG = my_tiles * 4;

    auto m_of = [&](int gg) -> long {
        return ((long)bid + (long)(gg >> 2) * G) * BM;
    };
    auto fullB  = [&](int s) -> uint32_t { return sb + OFF_BAR + s * 16; };
    auto emptyB = [&](int s) -> uint32_t { return sb + OFF_BAR + s * 16 + 8; };

    // ---- init barriers ----
    if (tid == 0) {
#pragma unroll
        for (int s = 0; s < A_STAGES; s++) {
            MBAR_INIT(fullB(s), 64);     // 64 producer threads arrive
            MBAR_INIT(emptyB(s), 256);   // 256 consumer threads arrive
        }
    }

    // ---- cooperative B load (once, resident) ----
    for (int i = tid; i < 8192; i += NTHREADS) {     // 8192 x 16B units
        const int c = i >> 11;            // chunk
        const int n = (i >> 3) & 255;     // B row
        const int u = i & 7;              // 16B unit in row
        uint32_t dst = sb + A_TOTAL + (uint32_t)c * B_CHUNK_BYTES +
                       n * 128 + ((u ^ (n & 7)) << 4);
        cp16(dst, g_Wt + n * KDIM + c * BK + u * 8);
    }
    cp_commit();
    cp_wait<0>();
    __syncthreads();     // B resident + barriers initialized, visible to all

    if (warp >= 8) {
        // ================= PRODUCER (warps 8,9: 64 threads) =================
        const int ptid  = tid - 256;
        const int a_f   = ptid & 15;          // float4 index along k
        const int a_r0  = ptid >> 4;          // 0..3; rows a_r0 + j*4
        const int u     = a_f >> 1;
        const int off8  = (a_f & 1) * 8;

        for (int gg = 0; gg < GG; gg++) {
            const int stage = gg & 3;
            const int phase = 1 ^ ((gg >> 2) & 1);    // start-flipped
            MBAR_WAIT(emptyB(stage), phase);

            const long m0 = m_of(gg);
            const int  k0 = (gg & 3) * BK;
            float4 v[32];
#pragma unroll
            for (int j = 0; j < 32; j++)
                v[j] = *(const float4*)(x + (m0 + a_r0 + j * 4) * KDIM + k0 + a_f * 4);

            const uint32_t aBase = sb + (uint32_t)stage * A_STAGE_BYTES;
#pragma unroll
            for (int j = 0; j < 32; j++) {
                const int row = a_r0 + j * 4;
                uint32_t addr = aBase + row * 128 + ((u ^ (row & 7)) << 4) + off8;
                __half2 h0 = __floats2half2_rn(v[j].x, v[j].y);
                __half2 h1 = __floats2half2_rn(v[j].z, v[j].w);
                asm volatile("st.shared.v2.b32 [%0], {%1, %2};"
                             :: "r"(addr), "r"(*(uint32_t*)&h0), "r"(*(uint32_t*)&h1));
            }
            MBAR_ARRIVE(fullB(stage));
        }
    } else {
        // ================= CONSUMER (warps 0..7: 256 threads) =================
        const int wm = warp & 1;          // 2 warps along M (64 rows)
        const int wn = warp >> 1;         // 4 warps along N (64 cols)
        // SMSP pair (warp, warp+4) skewed by 2 ks steps to desynchronize LDSM windows
        const int krot = (warp & 4) ? 2 : 0;

        const int la_row = (lane & 7) + ((lane >> 3) & 1) * 8;
        const int la_u   = lane >> 4;
        const int lb_row = (lane & 7) + ((lane >> 4) & 1) * 8;
        const int lb_u   = (lane >> 3) & 1;

        float acc[4][8][4];
#pragma unroll
        for (int mt = 0; mt < 4; mt++)
#pragma unroll
            for (int nt = 0; nt < 8; nt++)
#pragma unroll
                for (int i = 0; i < 4; i++) acc[mt][nt][i] = 0.f;

        for (int gg = 0; gg < GG; gg++) {
            const int stage = gg & 3;
            const int phase = (gg >> 2) & 1;
            MBAR_WAIT(fullB(stage), phase);

            const uint32_t aBase = sb + (uint32_t)stage * A_STAGE_BYTES;
            const uint32_t bBase = sb + A_TOTAL + (uint32_t)stage * B_CHUNK_BYTES;
#pragma unroll
            for (int ks0 = 0; ks0 < 4; ks0++) {
                const int ks = (ks0 + krot) & 3;      // per-warp K permutation
                const int u0 = ks * 2;
                uint32_t b[4][4];
#pragma unroll
                for (int nt2 = 0; nt2 < 4; nt2++) {
                    const int row = wn * 64 + nt2 * 16 + lb_row;
                    uint32_t addr = bBase + row * 128 + (((u0 + lb_u) ^ (row & 7)) << 4);
                    LDSM4(b[nt2][0], b[nt2][1], b[nt2][2], b[nt2][3], addr);
                }
#pragma unroll
                for (int mt = 0; mt < 4; mt++) {
                    uint32_t a[4];
                    const int row = wm * 64 + mt * 16 + la_row;
                    uint32_t addr = aBase + row * 128 + (((u0 + la_u) ^ (row & 7)) << 4);
                    LDSM4(a[0], a[1], a[2], a[3], addr);
#pragma unroll
                    for (int nt2 = 0; nt2 < 4; nt2++)
#pragma unroll
                        for (int s = 0; s < 2; s++) {
                            const int nt = nt2 * 2 + s;
                            mma_fp16(acc[mt][nt], a, b[nt2][2 * s], b[nt2][2 * s + 1]);
                        }
                }
            }
            MBAR_ARRIVE(emptyB(stage));   // stage consumed; producers may refill

            if ((gg & 3) == 3) {
                const long m0 = m_of(gg);
                const int er = lane >> 2;
                const int ec = (lane & 3) * 2;
#pragma unroll
                for (int mt = 0; mt < 4; mt++) {
                    const long r0 = m0 + wm * 64 + mt * 16 + er;
#pragma unroll
                    for (int nt = 0; nt < 8; nt++) {
                        const int col = wn * 64 + nt * 8 + ec;
                        *(float2*)(out + r0 * KDIM + col) =
                            make_float2(acc[mt][nt][0], acc[mt][nt][1]);
                        *(float2*)(out + (r0 + 8) * KDIM + col) =
                            make_float2(acc[mt][nt][2], acc[mt][nt][3]);
                    }
                }
#pragma unroll
                for (int mt = 0; mt < 4; mt++)
#pragma unroll
                    for (int nt = 0; nt < 8; nt++)
#pragma unroll
                        for (int i = 0; i < 4; i++) acc[mt][nt][i] = 0.f;
            }
        }
    }
}

extern "C" void kernel_launch(void* const* d_in, const int* in_sizes, int n_in,
                              void* d_out, int out_size) {
    const float* x = (const float*)d_in[0];
    const float* W = (const float*)d_in[1];
    float* out = (float*)d_out;

    const int M  = in_sizes[0] / KDIM;   // 401408
    const int NT = M / BM;               // 3136 tiles

    int nsm = 0;
    cudaDeviceGetAttribute(&nsm, cudaDevAttrMultiProcessorCount, 0);
    if (nsm <= 0) nsm = 148;
    if (nsm > NT) nsm = NT;

    cudaFuncSetAttribute(cp2d_fp16_kernel,
                         cudaFuncAttributeMaxDynamicSharedMemorySize, SMEM_TOTAL);

    dim3 pblk(32, 32), pgrd(KDIM / 32, KDIM / 32);
    prep_wt_kernel<<<pgrd, pblk>>>(W);
    cp2d_fp16_kernel<<<nsm, NTHREADS, SMEM_TOTAL>>>(x, out, nsm, NT);
}

// round 15
// speedup vs baseline: 1.4480x; 1.0253x over previous
#include <cuda_runtime.h>
#include <cuda_fp16.h>
#include <cstdint>

#define KDIM   256
#define BM     128
#define BN     256
#define BK     64

#define A_STAGE_BYTES (BM * BK * 2)            // 16384
#define A_TOTAL       (2 * A_STAGE_BYTES)      // 32768
#define B_CHUNK_BYTES (BN * BK * 2)            // 32768
#define B_TOTAL       (4 * B_CHUNK_BYTES)      // 131072
#define SMEM_TOTAL    (A_TOTAL + B_TOTAL)      // 163840

// ---------------- helpers ----------------
__device__ __forceinline__ uint32_t smem_u32(const void* p) {
    uint32_t a;
    asm("{ .reg .u64 t; cvta.to.shared.u64 t, %1; cvt.u32.u64 %0, t; }" : "=r"(a) : "l"(p));
    return a;
}
#define LDSM4(r0, r1, r2, r3, a)                                                 \
    asm volatile("ldmatrix.sync.aligned.m8n8.x4.shared.b16 {%0,%1,%2,%3}, [%4];" \
                 : "=r"(r0), "=r"(r1), "=r"(r2), "=r"(r3) : "r"(a))

__device__ __forceinline__ void mma_fp16(float* d, const uint32_t* a,
                                         uint32_t b0, uint32_t b1) {
    asm volatile(
        "mma.sync.aligned.m16n8k16.row.col.f32.f16.f16.f32 "
        "{%0,%1,%2,%3}, {%4,%5,%6,%7}, {%8,%9}, {%0,%1,%2,%3};"
        : "+f"(d[0]), "+f"(d[1]), "+f"(d[2]), "+f"(d[3])
        : "r"(a[0]), "r"(a[1]), "r"(a[2]), "r"(a[3]), "r"(b0), "r"(b1));
}

// ---------------- main GEMM: persistent CTAs, B resident (built in-kernel), 64x64 warp tile ----------------
__global__ __launch_bounds__(256, 1)
void cp2d_fp16_kernel(const float* __restrict__ x, const float* __restrict__ W,
                      float* __restrict__ out, int G, int NT) {
    extern __shared__ __align__(128) char smem[];
    const uint32_t sb = smem_u32(smem);

    const int tid  = threadIdx.x;
    const int lane = tid & 31;
    const int warp = tid >> 5;
    const int wm   = warp & 1;          // 2 warps along M (64 rows each)
    const int wn   = warp >> 1;         // 4 warps along N (64 cols each)
    const int bid  = blockIdx.x;

    const int my_tiles = (NT - bid + G - 1) / G;   // tiles: bid, bid+G, ...
    if (my_tiles <= 0) return;
    const int GG = my_tiles * 4;

    // A mapping: 128 rows x 16 float4 per chunk, 8/thread
    const int a_f   = tid & 15;
    const int a_row = tid >> 4;         // 0..15, rows += j*16

    // ldmatrix per-lane invariants
    const int la_row = (lane & 7) + ((lane >> 3) & 1) * 8;
    const int la_u   = lane >> 4;
    const int lb_row = (lane & 7) + ((lane >> 4) & 1) * 8;
    const int lb_u   = (lane >> 3) & 1;

    // ---- build resident B directly from W (fp32 [K,N] -> fp16 Wt[N,K], swizzled) ----
    {
        const int n = (warp << 5) + lane;          // 0..255, one n-row per thread
        const uint32_t swn = (uint32_t)(n & 7) << 4;
#pragma unroll
        for (int c = 0; c < 4; c++) {
            const uint32_t bBase = sb + A_TOTAL + (uint32_t)c * B_CHUNK_BYTES + n * 128;
#pragma unroll
            for (int u = 0; u < 8; u++) {
                float v[8];
#pragma unroll
                for (int j = 0; j < 8; j++)        // coalesced: lanes = consecutive n
                    v[j] = W[(c * 64 + u * 8 + j) * KDIM + n];
                __half2 h0 = __floats2half2_rn(v[0], v[1]);
                __half2 h1 = __floats2half2_rn(v[2], v[3]);
                __half2 h2 = __floats2half2_rn(v[4], v[5]);
                __half2 h3 = __floats2half2_rn(v[6], v[7]);
                uint32_t addr = bBase + (((uint32_t)u << 4) ^ swn);
                asm volatile("st.shared.v4.b32 [%0], {%1, %2, %3, %4};"
                             :: "r"(addr), "r"(*(uint32_t*)&h0), "r"(*(uint32_t*)&h1),
                                "r"(*(uint32_t*)&h2), "r"(*(uint32_t*)&h3));
            }
        }
    }

    float acc[4][8][4];
#pragma unroll
    for (int mt = 0; mt < 4; mt++)
#pragma unroll
        for (int nt = 0; nt < 8; nt++)
#pragma unroll
            for (int i = 0; i < 4; i++) acc[mt][nt][i] = 0.f;

    float4 rA[8];

    auto m_of = [&](int gg) -> long {
        return ((long)bid + (long)(gg >> 2) * G) * BM;
    };
    auto ldgA = [&](int gg) {
        const long m0 = m_of(gg);
        const int k0 = (gg & 3) * BK;
#pragma unroll
        for (int j = 0; j < 8; j++)
            rA[j] = *(const float4*)(x + (m0 + a_row + j * 16) * KDIM + k0 + a_f * 4);
    };
    auto stsA = [&](int st) {          // st = 0/1
        const uint32_t aBase = sb + (uint32_t)st * A_STAGE_BYTES;
        const int u = a_f >> 1, off8 = (a_f & 1) * 8;
#pragma unroll
        for (int j = 0; j < 8; j++) {
            const int row = a_row + j * 16;
            uint32_t addr = aBase + row * 128 + ((u ^ (row & 7)) << 4) + off8;
            __half2 h0 = __floats2half2_rn(rA[j].x, rA[j].y);
            __half2 h1 = __floats2half2_rn(rA[j].z, rA[j].w);
            asm volatile("st.shared.v2.b32 [%0], {%1, %2};"
                         :: "r"(addr), "r"(*(uint32_t*)&h0), "r"(*(uint32_t*)&h1));
        }
    };

    auto compute = [&](int st, int cb) {
        const uint32_t aBase = sb + (uint32_t)st * A_STAGE_BYTES;
        const uint32_t bBase = sb + A_TOTAL + (uint32_t)cb * B_CHUNK_BYTES;
#pragma unroll
        for (int ks = 0; ks < 4; ks++) {
            const int u0 = ks * 2;
            uint32_t b[4][4];
#pragma unroll
            for (int nt2 = 0; nt2 < 4; nt2++) {
                const int row = wn * 64 + nt2 * 16 + lb_row;
                uint32_t addr = bBase + row * 128 + (((u0 + lb_u) ^ (row & 7)) << 4);
                LDSM4(b[nt2][0], b[nt2][1], b[nt2][2], b[nt2][3], addr);
            }
#pragma unroll
            for (int mt = 0; mt < 4; mt++) {
                uint32_t a[4];
                const int row = wm * 64 + mt * 16 + la_row;
                uint32_t addr = aBase + row * 128 + (((u0 + la_u) ^ (row & 7)) << 4);
                LDSM4(a[0], a[1], a[2], a[3], addr);
#pragma unroll
                for (int nt2 = 0; nt2 < 4; nt2++)
#pragma unroll
                    for (int s = 0; s < 2; s++) {
                        const int nt = nt2 * 2 + s;
                        mma_fp16(acc[mt][nt], a, b[nt2][2 * s], b[nt2][2 * s + 1]);
                    }
            }
        }
    };

    // ---- prologue: stage A chunk 0 (B written above; sync covers both) ----
    ldgA(0);
    stsA(0);
    if (GG > 1) ldgA(1);
    __syncthreads();         // B + A stage0 visible

    // ---- unified chunk stream across all tiles ----
    for (int gg = 0; gg < GG; gg++) {
        const int st = gg & 1;
        if (gg + 1 < GG) {
            stsA(st ^ 1);                    // rA holds chunk gg+1
            if (gg + 2 < GG) ldgA(gg + 2);
        }
        compute(st, gg & 3);

        if ((gg & 3) == 3) {
            const long m0 = m_of(gg);
            const int er = lane >> 2;
            const int ec = (lane & 3) * 2;
#pragma unroll
            for (int mt = 0; mt < 4; mt++) {
                const long r0 = m0 + wm * 64 + mt * 16 + er;
#pragma unroll
                for (int nt = 0; nt < 8; nt++) {
                    const int col = wn * 64 + nt * 8 + ec;
                    *(float2*)(out + r0 * KDIM + col) =
                        make_float2(acc[mt][nt][0], acc[mt][nt][1]);
                    *(float2*)(out + (r0 + 8) * KDIM + col) =
                        make_float2(acc[mt][nt][2], acc[mt][nt][3]);
                }
            }
#pragma unroll
            for (int mt = 0; mt < 4; mt++)
#pragma unroll
                for (int nt = 0; nt < 8; nt++)
#pragma unroll
                    for (int i = 0; i < 4; i++) acc[mt][nt][i] = 0.f;
        }
        if (gg + 1 < GG) __syncthreads();    // stage (gg+1)&1 ready / WAR guard
    }
}

extern "C" void kernel_launch(void* const* d_in, const int* in_sizes, int n_in,
                              void* d_out, int out_size) {
    const float* x = (const float*)d_in[0];
    const float* W = (const float*)d_in[1];
    float* out = (float*)d_out;

    const int M  = in_sizes[0] / KDIM;   // 401408
    const int NT = M / BM;               // 3136 tiles

    int nsm = 0;
    cudaDeviceGetAttribute(&nsm, cudaDevAttrMultiProcessorCount, 0);
    if (nsm <= 0) nsm = 148;
    if (nsm > NT) nsm = NT;

    cudaFuncSetAttribute(cp2d_fp16_kernel,
                         cudaFuncAttributeMaxDynamicSharedMemorySize, SMEM_TOTAL);

    cp2d_fp16_kernel<<<nsm, 256, SMEM_TOTAL>>>(x, W, out, nsm, NT);
}